// round 10
// baseline (speedup 1.0000x reference)
#include <cuda_runtime.h>
#include <cstdint>

// EfficientSHRFFN — bit-exact semantics (locked in R4, rel_err == 0.0):
//   B=262144, NPOS=4, D=64; opcode=3, OP_START=16 -> op_active idx 19
//   NIB_A=0, NIB_B=1, RESULT=2
//   value f32 sum order: strided halving (t0+t2)+(t1+t3), products exact
//   astype(int64) under x64-disabled jax -> int32, float->int32 SATURATES
//   shifts/byte-extract in int32
//
// R10 structural change: stride-16-within-row mapping. Lane r in [0,16)
// of each warp-half loads f4[row*64 + r + 16*i], i=0..3. The r==0 lane then
// owns ALL inputs of the row's compute in registers (a_p = v[p].x, shift =
// v[0].y); op (f4[4].w) comes from lane r==4 via one shfl. This deletes the
// 6 redundant scalar LDGs per computing thread of earlier rounds.

static constexpr long long N_ROWS = 262144;   // B
static constexpr int THREADS      = 256;      // 8 warps -> 16 rows per block

__global__ void __launch_bounds__(THREADS)
shrffn_kernel(const float4* __restrict__ in4,
              float4* __restrict__ out4)
{
    const int lane = threadIdx.x & 31;
    const int r    = lane & 15;                       // position within row-half
    const long long warp_id = (long long)blockIdx.x * (THREADS / 32)
                            + (threadIdx.x >> 5);
    const long long row  = warp_id * 2 + (lane >> 4); // 2 rows per warp
    const long long base = row * 64 + r;              // float4 index

    // 4 independent 128-bit loads (MLP=4), fully coalesced: per i, each
    // warp-half covers a contiguous 256B span.
    float4 v[4];
#pragma unroll
    for (int i = 0; i < 4; i++) {
        v[i] = in4[base + 16 * i];
    }

    // op_active = element 19 of the row = f4[row*64 + 4].w, held by lane r==4
    // of the same warp-half. Broadcast (all lanes participate).
    float op = __shfl_sync(0xffffffffu, v[0].w, (lane & 16) | 4);

    if (r == 0) {
        // All row inputs are already in registers.
        float a0 = v[0].x;           // in[row*256 + 0]
        float a1 = v[1].x;           // in[row*256 + 64]
        float a2 = v[2].x;           // in[row*256 + 128]
        float a3 = v[3].x;           // in[row*256 + 192]
        float sh_f = v[0].y;         // in[row*256 + 1]

        // Strided-halving tree: (t0+t2) + (t1+t3); products exact.
        float t1 = a1 * 256.0f;
        float t2 = a2 * 65536.0f;
        float t3 = a3 * 16777216.0f;
        float val = __fadd_rn(__fadd_rn(a0, t2), __fadd_rn(t1, t3));

        int value_i = (int)val;      // saturating cvt.rzi.s32.f32

        int shift = (int)sh_f;
        if (shift < 0)  shift = 0;
        if (shift > 31) shift = 31;

        int shifted = value_i >> shift;

#pragma unroll
        for (int p = 0; p < 4; p++) {
            v[p].z = (float)((shifted >> (8 * p)) & 255) * op;
        }
    }

#pragma unroll
    for (int i = 0; i < 4; i++) {
        out4[base + 16 * i] = v[i];
    }
}

extern "C" void kernel_launch(void* const* d_in, const int* in_sizes, int n_in,
                              void* d_out, int out_size)
{
    const float* x = (const float*)d_in[0];
    float* out = (float*)d_out;

    // 2 rows per warp, 8 warps per block -> 16 rows per block
    const int blocks = (int)(N_ROWS / 16);            // 16384, exact division

    shrffn_kernel<<<blocks, THREADS>>>((const float4*)x, (float4*)out);
}